// round 6
// baseline (speedup 1.0000x reference)
#include <cuda_runtime.h>
#include <cuda_bf16.h>
#include <cstdint>
#include <cstddef>

// ---------------- problem constants ----------------
#define BB 4
#define NN 2000
#define GG 20
#define ROWS (BB*NN)          // 8000
#define PADM 8064             // 63 * 128
#define FEAT 12544            // 256*7*7
#define HID 1024
#define NCLS 81
#define HEADN 256             // padded head output width (85 used)
#define THR 0.5f
#define NUM_POS 128
#define NUM_NEG 384
#define DENOM 2048.0f

// ---------------- scratch (static device memory; no allocs) ----------------
__device__ __nv_bfloat16 g_W1t [(size_t)HID * FEAT];
__device__ __nv_bfloat16 g_W2t [(size_t)HID * HID];
__device__ __nv_bfloat16 g_Wcbt[(size_t)HEADN * HID];
__device__ float         g_bcb [HEADN];
__device__ __nv_bfloat16 g_h1b [(size_t)PADM * HID];
__device__ __nv_bfloat16 g_h2b [(size_t)PADM * HID];
__device__ float         g_logits[(size_t)PADM * HEADN];
__device__ int   g_label[ROWS];
__device__ float g_mbox[ROWS * 4];
__device__ int   g_samp[ROWS];
__device__ float g_loss[2];

// ---------------- PTX helpers (sm_80+ portable) ----------------
__device__ __forceinline__ uint32_t s2u(const void* p) {
    uint32_t r;
    asm("{ .reg .u64 t; cvta.to.shared.u64 t, %1; cvt.u32.u64 %0, t; }"
        : "=r"(r) : "l"(p));
    return r;
}
__device__ __forceinline__ void cpa16(uint32_t dst, const void* src) {
    asm volatile("cp.async.cg.shared.global [%0], [%1], 16;" :: "r"(dst), "l"(src));
}
__device__ __forceinline__ void cpa_commit() {
    asm volatile("cp.async.commit_group;" ::: "memory");
}
template<int N>
__device__ __forceinline__ void cpa_wait() {
    asm volatile("cp.async.wait_group %0;" :: "n"(N) : "memory");
}
__device__ __forceinline__ void ldmx4(uint32_t* r, uint32_t addr) {
    asm volatile("ldmatrix.sync.aligned.m8n8.x4.shared.b16 {%0,%1,%2,%3}, [%4];"
        : "=r"(r[0]), "=r"(r[1]), "=r"(r[2]), "=r"(r[3]) : "r"(addr));
}
__device__ __forceinline__ void mma16816(float* c, const uint32_t* a, const uint32_t* b) {
    asm volatile(
        "mma.sync.aligned.m16n8k16.row.col.f32.bf16.bf16.f32 "
        "{%0,%1,%2,%3}, {%4,%5,%6,%7}, {%8,%9}, {%0,%1,%2,%3};"
        : "+f"(c[0]), "+f"(c[1]), "+f"(c[2]), "+f"(c[3])
        : "r"(a[0]), "r"(a[1]), "r"(a[2]), "r"(a[3]), "r"(b[0]), "r"(b[1]));
}
__device__ __forceinline__ uint32_t packbf2(float a, float b) {
    __nv_bfloat162 h = __floats2bfloat162_rn(a, b);
    return *(uint32_t*)&h;
}

// ---------------- bf16 mma.sync GEMM, BM=128 BN=256 BK=64, 512 thr ----------
// AFP32=1: A is fp32 (X), converted in-register in the producer (2-slot ring).
// AFP32=0: A is bf16, 3-stage cp.async like B.
#define BSTAGES 3
#define ATILE 16384           // 128x64 bf16
#define BTILE 32768           // 256x64 bf16

template<int AFP32, int RELU, int BF16OUT>
__global__ __launch_bounds__(512, 1)
void gemm_mma(const void* __restrict__ Avoid, int lda,
              const __nv_bfloat16* __restrict__ Bw, int ldb,
              const float* __restrict__ bias,
              void* __restrict__ Cout, int ldc, int K)
{
    extern __shared__ __align__(1024) char dsmem[];
    const uint32_t tile0 = s2u(dsmem);
    const uint32_t ASZ = AFP32 ? 2 * ATILE : 3 * ATILE;
    const uint32_t bOff = ASZ;

    const int tid = threadIdx.x;
    const int wid = tid >> 5;
    const int lid = tid & 31;
    const int warpM = wid >> 3;        // 0..1
    const int warpN = wid & 7;         // 0..7

    const int rowBase = blockIdx.y * 128;
    const int colBase = blockIdx.x * 256;
    const int CH = K >> 6;

    // ---- B producer: 256 rows x 128B per stage; 512 thr x 4 chunks ----
    #define LOAD_B(c)                                                              \
    {                                                                              \
        const uint32_t bD_ = tile0 + bOff + ((c) % BSTAGES) * BTILE;               \
        _Pragma("unroll")                                                          \
        for (int i_ = 0; i_ < 4; i_++) {                                           \
            int idx_ = tid + i_ * 512;                                             \
            int row_ = idx_ >> 3, c16_ = idx_ & 7;                                 \
            uint32_t off_ = row_ * 128 + (((c16_ ^ (row_ & 7)) << 4));             \
            cpa16(bD_ + off_, Bw + (size_t)(colBase + row_) * ldb + (c) * 64 + c16_ * 8); \
        }                                                                          \
    }
    // ---- A producer (bf16 path): 128 rows x 128B; 512 thr x 2 chunks ----
    #define LOAD_A16(c)                                                            \
    {                                                                              \
        const __nv_bfloat16* Ab_ = (const __nv_bfloat16*)Avoid;                    \
        const uint32_t aD_ = tile0 + ((c) % BSTAGES) * ATILE;                      \
        _Pragma("unroll")                                                          \
        for (int i_ = 0; i_ < 2; i_++) {                                           \
            int idx_ = tid + i_ * 512;                                             \
            int row_ = idx_ >> 3, c16_ = idx_ & 7;                                 \
            uint32_t off_ = row_ * 128 + (((c16_ ^ (row_ & 7)) << 4));             \
            cpa16(aD_ + off_, Ab_ + (size_t)(rowBase + row_) * lda + (c) * 64 + c16_ * 8); \
        }                                                                          \
    }

    // ---- fp32 A path state ----
    const int arow = tid >> 2;          // 0..127
    const int colq = tid & 3;           // 0..3 (16-float slice)
    const bool rowok = AFP32 ? ((rowBase + arow) < ROWS) : false;
    const float* aF = AFP32
        ? ((const float*)Avoid + (size_t)(rowBase + arow) * lda + colq * 16)
        : nullptr;
    const uint32_t aoff0 = arow * 128 + ((((colq * 2)     ^ (arow & 7)) << 4));
    const uint32_t aoff1 = arow * 128 + ((((colq * 2 + 1) ^ (arow & 7)) << 4));
    float4 f0, f1, f2, f3;              // staged 16 floats (chunk c+1)

    #define LDG_A32(c)                                                             \
    {                                                                              \
        if (rowok) {                                                               \
            const float* p_ = aF + (c) * 64;                                       \
            f0 = *(const float4*)(p_);                                             \
            f1 = *(const float4*)(p_ + 4);                                         \
            f2 = *(const float4*)(p_ + 8);                                         \
            f3 = *(const float4*)(p_ + 12);                                        \
        } else {                                                                   \
            f0 = f1 = f2 = f3 = make_float4(0.f, 0.f, 0.f, 0.f);                   \
        }                                                                          \
    }
    #define STS_A32(c)                                                             \
    {                                                                              \
        char* base_ = dsmem + ((c) & 1) * ATILE;                                   \
        uint4 u0_, u1_;                                                            \
        u0_.x = packbf2(f0.x, f0.y); u0_.y = packbf2(f0.z, f0.w);                  \
        u0_.z = packbf2(f1.x, f1.y); u0_.w = packbf2(f1.z, f1.w);                  \
        u1_.x = packbf2(f2.x, f2.y); u1_.y = packbf2(f2.z, f2.w);                  \
        u1_.z = packbf2(f3.x, f3.y); u1_.w = packbf2(f3.z, f3.w);                  \
        *(uint4*)(base_ + aoff0) = u0_;                                            \
        *(uint4*)(base_ + aoff1) = u1_;                                            \
    }

    // ---- prologue ----
    if (AFP32) {
        LDG_A32(0);
        STS_A32(0);
        if (CH > 1) LDG_A32(1);
        LOAD_B(0); cpa_commit();
        if (CH > 1) LOAD_B(1); cpa_commit();
    } else {
        LOAD_A16(0); LOAD_B(0); cpa_commit();
        if (CH > 1) { LOAD_A16(1); LOAD_B(1); } cpa_commit();
    }

    float acc[4][4][4];
    #pragma unroll
    for (int i = 0; i < 4; i++)
        #pragma unroll
        for (int j = 0; j < 4; j++)
            #pragma unroll
            for (int e = 0; e < 4; e++) acc[i][j][e] = 0.f;

    // ldmatrix lane geometry
    const int aRowIn = (lid & 7) + ((lid & 8) ? 8 : 0);
    const int aC16add = (lid >> 4) & 1;
    const int bRowIn = (lid & 7) + ((lid >= 16) ? 8 : 0);
    const int bC16add = (lid >> 3) & 1;

    int aRow[4], bRow[2];
    #pragma unroll
    for (int i = 0; i < 4; i++) aRow[i] = warpM * 64 + i * 16 + aRowIn;
    #pragma unroll
    for (int j = 0; j < 2; j++) bRow[j] = warpN * 32 + j * 16 + bRowIn;

    for (int c = 0; c < CH; c++) {
        cpa_wait<1>();
        __syncthreads();

        // producers for chunk c+2 (and STS of staged A chunk c+1)
        if (AFP32) {
            if (c + 2 < CH) LOAD_B(c + 2);
            cpa_commit();
            if (c + 1 < CH) {
                STS_A32(c + 1);
                if (c + 2 < CH) LDG_A32(c + 2);
            }
        } else {
            if (c + 2 < CH) { LOAD_A16(c + 2); LOAD_B(c + 2); }
            cpa_commit();
        }

        const uint32_t aB = tile0 + (AFP32 ? ((c & 1) * ATILE) : ((c % BSTAGES) * ATILE));
        const uint32_t bB = tile0 + bOff + (c % BSTAGES) * BTILE;

        #pragma unroll
        for (int ks = 0; ks < 4; ks++) {
            uint32_t aFr[4][4], bFr[2][4];
            #pragma unroll
            for (int i = 0; i < 4; i++) {
                int c16 = ks * 2 + aC16add;
                ldmx4(aFr[i], aB + aRow[i] * 128 + (((c16 ^ (aRow[i] & 7)) << 4)));
            }
            #pragma unroll
            for (int j = 0; j < 2; j++) {
                int c16 = ks * 2 + bC16add;
                ldmx4(bFr[j], bB + bRow[j] * 128 + (((c16 ^ (bRow[j] & 7)) << 4)));
            }
            #pragma unroll
            for (int i = 0; i < 4; i++)
                #pragma unroll
                for (int jj = 0; jj < 4; jj++)
                    mma16816(acc[i][jj], aFr[i], &bFr[jj >> 1][(jj & 1) * 2]);
        }
        __syncthreads();
    }

    // ---- epilogue ----
    const int rq = lid >> 2;
    const int cq = (lid & 3) * 2;
    #pragma unroll
    for (int i = 0; i < 4; i++) {
        int m0 = rowBase + warpM * 64 + i * 16 + rq;
        #pragma unroll
        for (int j = 0; j < 4; j++) {
            int col = colBase + warpN * 32 + j * 8 + cq;
            float b0 = bias[col], b1 = bias[col + 1];
            float v00 = acc[i][j][0] + b0, v01 = acc[i][j][1] + b1;
            float v10 = acc[i][j][2] + b0, v11 = acc[i][j][3] + b1;
            if (RELU) {
                v00 = fmaxf(v00, 0.f); v01 = fmaxf(v01, 0.f);
                v10 = fmaxf(v10, 0.f); v11 = fmaxf(v11, 0.f);
            }
            if (BF16OUT) {
                __nv_bfloat16* O = (__nv_bfloat16*)Cout;
                *(__nv_bfloat162*)(O + (size_t)m0 * ldc + col)       = __floats2bfloat162_rn(v00, v01);
                *(__nv_bfloat162*)(O + (size_t)(m0 + 8) * ldc + col) = __floats2bfloat162_rn(v10, v11);
            } else {
                float* O = (float*)Cout;
                *(float2*)(O + (size_t)m0 * ldc + col)       = make_float2(v00, v01);
                *(float2*)(O + (size_t)(m0 + 8) * ldc + col) = make_float2(v10, v11);
            }
        }
    }
    #undef LOAD_B
    #undef LOAD_A16
    #undef LDG_A32
    #undef STS_A32
}

#define SMEM_AFP32 (2 * ATILE + BSTAGES * BTILE)   // 128KB
#define SMEM_A16   (3 * ATILE + BSTAGES * BTILE)   // 144KB

// ---------------- prep kernels ----------------
__global__ void transpose_bf16(const float* __restrict__ in, __nv_bfloat16* __restrict__ out,
                               int R, int C) {
    __shared__ float t[32][33];
    int c0 = blockIdx.x * 32, r0 = blockIdx.y * 32;
    int tx = threadIdx.x, ty = threadIdx.y;
    for (int dy = 0; dy < 32; dy += 8)
        t[ty + dy][tx] = in[(size_t)(r0 + ty + dy) * C + c0 + tx];
    __syncthreads();
    for (int dy = 0; dy < 32; dy += 8)
        out[(size_t)(c0 + ty + dy) * R + r0 + tx] = __float2bfloat16_rn(t[tx][ty + dy]);
}

__global__ void pack_head(const float* __restrict__ Wc, const float* __restrict__ bc,
                          const float* __restrict__ Wb, const float* __restrict__ bb) {
    int i = blockIdx.x * blockDim.x + threadIdx.x;
    if (i < HEADN * HID) {
        int n = i / HID, k = i % HID;
        float v = 0.f;
        if (n < NCLS) v = Wc[(size_t)k * NCLS + n];
        else if (n < NCLS + 4) v = Wb[(size_t)k * 4 + (n - NCLS)];
        g_Wcbt[i] = __float2bfloat16_rn(v);
    }
    if (i < HEADN) {
        float v = 0.f;
        if (i < NCLS) v = bc[i];
        else if (i < NCLS + 4) v = bb[i - NCLS];
        g_bcb[i] = v;
    }
}

// ---------------- labeling / sampling ----------------
__global__ void zero_kernel() { g_loss[0] = 0.f; g_loss[1] = 0.f; }

__global__ void assign_kernel(const float* __restrict__ prop,
                              const float* __restrict__ gtb,
                              const int*   __restrict__ gtl) {
    int idx = blockIdx.x * blockDim.x + threadIdx.x;
    if (idx >= ROWS) return;
    int b = idx / NN;
    const float* p = prop + (size_t)idx * 4;
    float px1 = p[0], py1 = p[1], px2 = p[2], py2 = p[3];
    float ap = (px2 - px1) * (py2 - py1);
    float best = -1e30f; int bi = 0;
    for (int g = 0; g < GG; g++) {
        const float* gb = gtb + (size_t)(b * GG + g) * 4;
        float x1 = fmaxf(px1, gb[0]);
        float y1 = fmaxf(py1, gb[1]);
        float x2 = fminf(px2, gb[2]);
        float y2 = fminf(py2, gb[3]);
        float inter = fmaxf(x2 - x1, 0.f) * fmaxf(y2 - y1, 0.f);
        float ag = (gb[2] - gb[0]) * (gb[3] - gb[1]);
        float iou = inter / (ap + ag - inter);
        if (iou > best) { best = iou; bi = g; }
    }
    bool fg = best > THR;
    g_label[idx] = fg ? gtl[b * GG + bi] : 0;
    const float* gb = gtb + (size_t)(b * GG + bi) * 4;
    g_mbox[idx * 4 + 0] = fg ? gb[0] : 0.f;
    g_mbox[idx * 4 + 1] = fg ? gb[1] : 0.f;
    g_mbox[idx * 4 + 2] = fg ? gb[2] : 0.f;
    g_mbox[idx * 4 + 3] = fg ? gb[3] : 0.f;
}

__global__ __launch_bounds__(1024) void sample_kernel() {
    int b = blockIdx.x;
    __shared__ int sp[2048];
    __shared__ int sn[2048];
    int tid = threadIdx.x;
    int i0 = tid, i1 = tid + 1024;
    int l0 = (i0 < NN) ? g_label[b * NN + i0] : -1;
    int l1 = (i1 < NN) ? g_label[b * NN + i1] : -1;
    sp[i0] = (i0 < NN && l0 >= 1) ? 1 : 0;
    sn[i0] = (i0 < NN && l0 == 0) ? 1 : 0;
    sp[i1] = (i1 < NN && l1 >= 1) ? 1 : 0;
    sn[i1] = (i1 < NN && l1 == 0) ? 1 : 0;
    __syncthreads();
    for (int off = 1; off < 2048; off <<= 1) {
        int a0 = (i0 >= off) ? sp[i0 - off] : 0;
        int c0 = (i0 >= off) ? sn[i0 - off] : 0;
        int a1 = (i1 >= off) ? sp[i1 - off] : 0;
        int c1 = (i1 >= off) ? sn[i1 - off] : 0;
        __syncthreads();
        sp[i0] += a0; sn[i0] += c0; sp[i1] += a1; sn[i1] += c1;
        __syncthreads();
    }
    if (i0 < NN) {
        bool kp = (l0 >= 1) && (sp[i0] <= NUM_POS);
        bool kn = (l0 == 0) && (sn[i0] <= NUM_NEG);
        g_samp[b * NN + i0] = kp ? l0 : (kn ? 0 : -1);
    }
    if (i1 < NN) {
        bool kp = (l1 >= 1) && (sp[i1] <= NUM_POS);
        bool kn = (l1 == 0) && (sn[i1] <= NUM_NEG);
        g_samp[b * NN + i1] = kp ? l1 : (kn ? 0 : -1);
    }
}

// ---------------- per-row loss ----------------
__global__ void loss_kernel(const float* __restrict__ prop) {
    int r = blockIdx.x * blockDim.x + threadIdx.x;
    if (r >= ROWS) return;
    const float* lg = g_logits + (size_t)r * HEADN;

    float mx = -1e30f;
    for (int c = 0; c < NCLS; c++) mx = fmaxf(mx, lg[c]);
    float s = 0.f;
    float p[NCLS];
    for (int c = 0; c < NCLS; c++) { p[c] = expf(lg[c] - mx); s += p[c]; }
    float inv = 1.f / s;
    for (int c = 0; c < NCLS; c++) p[c] *= inv;
    float mx2 = -1e30f;
    for (int c = 0; c < NCLS; c++) mx2 = fmaxf(mx2, p[c]);
    float s2 = 0.f;
    for (int c = 0; c < NCLS; c++) s2 += expf(p[c] - mx2);
    float logZ = mx2 + logf(s2);

    int sv = g_samp[r];
    int tgt = sv > 0 ? sv : 0;
    float cls = (sv >= 0) ? (logZ - p[tgt]) : 0.f;

    float loc = 0.f;
    if (sv > 0) {
        const float* pb = prop + (size_t)r * 4;
        const float* gb = g_mbox + (size_t)r * 4;
        float pw  = pb[2] - pb[0];
        float ph  = pb[3] - pb[1];
        float pcx = pb[0] + 0.5f * pw;
        float pcy = pb[1] + 0.5f * ph;
        float gw  = gb[2] - gb[0];
        float gh  = gb[3] - gb[1];
        float gcx = 0.5f * (gb[0] + gb[2]);
        float gcy = 0.5f * (gb[1] + gb[3]);
        float gt_d[4];
        gt_d[0] = (gcx - pcx) / pw;
        gt_d[1] = (gcy - pcy) / ph;
        gt_d[2] = logf(gw / pw);
        gt_d[3] = logf(gh / ph);
        for (int c = 0; c < 4; c++) {
            float d  = lg[NCLS + c] - gt_d[c];
            float ad = fabsf(d);
            loc += (ad < 1.f) ? 0.5f * d * d : (ad - 0.5f);
        }
    }
    if (cls != 0.f) atomicAdd(&g_loss[0], cls);
    if (loc != 0.f) atomicAdd(&g_loss[1], loc);
}

__global__ void finalize_kernel(float* out) {
    out[0] = g_loss[0] / DENOM;
    out[1] = g_loss[1] / DENOM;
}

// ---------------- launch -----------------------------------------------------
extern "C" void kernel_launch(void* const* d_in, const int* in_sizes, int n_in,
                              void* d_out, int out_size) {
    const float* X    = (const float*)d_in[0];
    const float* prop = (const float*)d_in[1];
    const float* gtb  = (const float*)d_in[2];
    const int*   gtl  = (const int*)  d_in[3];
    const float* W1   = (const float*)d_in[4];
    const float* b1   = (const float*)d_in[5];
    const float* W2   = (const float*)d_in[6];
    const float* b2   = (const float*)d_in[7];
    const float* Wc   = (const float*)d_in[8];
    const float* bc   = (const float*)d_in[9];
    const float* Wb   = (const float*)d_in[10];
    const float* bb   = (const float*)d_in[11];
    float* out = (float*)d_out;

    void *pW1t, *pW2t, *pWcbt, *pbcb, *ph1, *ph2, *plg;
    cudaGetSymbolAddress(&pW1t, g_W1t);
    cudaGetSymbolAddress(&pW2t, g_W2t);
    cudaGetSymbolAddress(&pWcbt, g_Wcbt);
    cudaGetSymbolAddress(&pbcb, g_bcb);
    cudaGetSymbolAddress(&ph1, g_h1b);
    cudaGetSymbolAddress(&ph2, g_h2b);
    cudaGetSymbolAddress(&plg, g_logits);

    cudaFuncSetAttribute(gemm_mma<1, 1, 1>, cudaFuncAttributeMaxDynamicSharedMemorySize, SMEM_AFP32);
    cudaFuncSetAttribute(gemm_mma<0, 1, 1>, cudaFuncAttributeMaxDynamicSharedMemorySize, SMEM_A16);
    cudaFuncSetAttribute(gemm_mma<0, 0, 0>, cudaFuncAttributeMaxDynamicSharedMemorySize, SMEM_A16);

    transpose_bf16<<<dim3(HID / 32, FEAT / 32), dim3(32, 8)>>>(W1, (__nv_bfloat16*)pW1t, FEAT, HID);
    transpose_bf16<<<dim3(HID / 32, HID / 32), dim3(32, 8)>>>(W2, (__nv_bfloat16*)pW2t, HID, HID);
    pack_head<<<(HEADN * HID + 255) / 256, 256>>>(Wc, bc, Wb, bb);

    zero_kernel<<<1, 1>>>();
    assign_kernel<<<(ROWS + 255) / 256, 256>>>(prop, gtb, gtl);
    sample_kernel<<<BB, 1024>>>();

    // GEMM1: fp32 X fused-convert, bf16 out + relu
    gemm_mma<1, 1, 1><<<dim3(HID / 256, PADM / 128), 512, SMEM_AFP32>>>(
        (const void*)X, FEAT, (const __nv_bfloat16*)pW1t, FEAT,
        b1, ph1, HID, FEAT);
    // GEMM2: bf16 in/out + relu
    gemm_mma<0, 1, 1><<<dim3(HID / 256, PADM / 128), 512, SMEM_A16>>>(
        ph1, HID, (const __nv_bfloat16*)pW2t, HID,
        b2, ph2, HID, HID);
    // head: bf16 in, fp32 logits out, no relu
    gemm_mma<0, 0, 0><<<dim3(HEADN / 256, PADM / 128), 512, SMEM_A16>>>(
        ph2, HID, (const __nv_bfloat16*)pWcbt, HID,
        (const float*)pbcb, plg, HEADN, HID);

    loss_kernel<<<(ROWS + 255) / 256, 256>>>(prop);
    finalize_kernel<<<1, 1>>>(out);
}

// round 7
// speedup vs baseline: 1.8510x; 1.8510x over previous
#include <cuda_runtime.h>
#include <cuda_bf16.h>
#include <cstdint>
#include <cstddef>

// ---------------- problem constants ----------------
#define BB 4
#define NN 2000
#define GG 20
#define ROWS (BB*NN)          // 8000
#define PADM 8064             // 63 * 128
#define FEAT 12544            // 256*7*7
#define HID 1024
#define NCLS 81
#define HEADN 256             // padded head output width (85 used)
#define THR 0.5f
#define NUM_POS 128
#define NUM_NEG 384
#define DENOM 2048.0f

// ---------------- scratch (static device memory; no allocs) ----------------
// NOTE: __device__ globals are zero-initialized at module load. Pad rows of
// g_Xb (8000..8063) are NEVER written and stay zero — deterministic.
__device__ __nv_bfloat16 g_Xb  [(size_t)PADM * FEAT];
__device__ __nv_bfloat16 g_W1t [(size_t)HID * FEAT];
__device__ __nv_bfloat16 g_W2t [(size_t)HID * HID];
__device__ __nv_bfloat16 g_Wcbt[(size_t)HEADN * HID];
__device__ float         g_bcb [HEADN];
__device__ __nv_bfloat16 g_h1b [(size_t)PADM * HID];
__device__ __nv_bfloat16 g_h2b [(size_t)PADM * HID];
__device__ float         g_logits[(size_t)PADM * HEADN];
__device__ int   g_label[ROWS];
__device__ float g_mbox[ROWS * 4];
__device__ int   g_samp[ROWS];
__device__ float g_loss[2];
__device__ unsigned g_done;

// ---------------- PTX helpers (sm_80+ portable) ----------------
__device__ __forceinline__ uint32_t s2u(const void* p) {
    uint32_t r;
    asm("{ .reg .u64 t; cvta.to.shared.u64 t, %1; cvt.u32.u64 %0, t; }"
        : "=r"(r) : "l"(p));
    return r;
}
__device__ __forceinline__ void cpa16(uint32_t dst, const void* src) {
    asm volatile("cp.async.cg.shared.global [%0], [%1], 16;" :: "r"(dst), "l"(src));
}
__device__ __forceinline__ void cpa_commit() {
    asm volatile("cp.async.commit_group;" ::: "memory");
}
template<int N>
__device__ __forceinline__ void cpa_wait() {
    asm volatile("cp.async.wait_group %0;" :: "n"(N) : "memory");
}
__device__ __forceinline__ void ldmx4(uint32_t* r, uint32_t addr) {
    asm volatile("ldmatrix.sync.aligned.m8n8.x4.shared.b16 {%0,%1,%2,%3}, [%4];"
        : "=r"(r[0]), "=r"(r[1]), "=r"(r[2]), "=r"(r[3]) : "r"(addr));
}
__device__ __forceinline__ void mma16816(float* c, const uint32_t* a, const uint32_t* b) {
    asm volatile(
        "mma.sync.aligned.m16n8k16.row.col.f32.bf16.bf16.f32 "
        "{%0,%1,%2,%3}, {%4,%5,%6,%7}, {%8,%9}, {%0,%1,%2,%3};"
        : "+f"(c[0]), "+f"(c[1]), "+f"(c[2]), "+f"(c[3])
        : "r"(a[0]), "r"(a[1]), "r"(a[2]), "r"(a[3]), "r"(b[0]), "r"(b[1]));
}

// ---------------- bf16 mma.sync GEMM (R4-proven config) ---------------------
// C[M,Ntot] = act(A[M,K] @ Bw[Ntot,K]^T + bias)
// BM=128, BN=128, BK=64 (128B rows, XOR-8 swizzle), 3 stages, 256 threads.
#define STAGES 3
#define ATILE 16384
#define STAGE_BYTES 32768
#define GEMM_SMEM (STAGES * STAGE_BYTES)

template<int RELU, int BF16OUT>
__global__ __launch_bounds__(256, 2)
void gemm_mma(const __nv_bfloat16* __restrict__ A, int lda,
              const __nv_bfloat16* __restrict__ Bw, int ldb,
              const float* __restrict__ bias,
              void* __restrict__ Cout, int ldc, int K)
{
    extern __shared__ __align__(1024) char dsmem[];
    const uint32_t tile0 = s2u(dsmem);

    const int tid = threadIdx.x;
    const int wid = tid >> 5;
    const int lid = tid & 31;
    const int warpM = wid >> 2;        // 0..1  (64-row slab)
    const int warpN = wid & 3;         // 0..3  (32-col slab)

    const int rowBase = blockIdx.y * 128;
    const int colBase = blockIdx.x * 128;
    const int CH = K >> 6;

    #define LOAD_STAGE(c)                                                          \
    {                                                                              \
        const int slot_ = (c) % STAGES;                                            \
        const uint32_t aD_ = tile0 + slot_ * STAGE_BYTES;                          \
        const uint32_t bD_ = aD_ + ATILE;                                          \
        _Pragma("unroll")                                                          \
        for (int i_ = 0; i_ < 4; i_++) {                                           \
            int idx_ = tid + i_ * 256;                                             \
            int row_ = idx_ >> 3, c16_ = idx_ & 7;                                 \
            uint32_t off_ = row_ * 128 + (((c16_ ^ (row_ & 7)) << 4));             \
            cpa16(aD_ + off_, A  + (size_t)(rowBase + row_) * lda + (c) * 64 + c16_ * 8); \
            cpa16(bD_ + off_, Bw + (size_t)(colBase + row_) * ldb + (c) * 64 + c16_ * 8); \
        }                                                                          \
        cpa_commit();                                                              \
    }

    LOAD_STAGE(0);
    LOAD_STAGE(1);

    float acc[4][4][4];
    #pragma unroll
    for (int i = 0; i < 4; i++)
        #pragma unroll
        for (int j = 0; j < 4; j++)
            #pragma unroll
            for (int e = 0; e < 4; e++) acc[i][j][e] = 0.f;

    const int aRowIn = (lid & 7) + ((lid & 8) ? 8 : 0);
    const int aC16add = (lid >> 4) & 1;
    const int bRowIn = (lid & 7) + ((lid >= 16) ? 8 : 0);
    const int bC16add = (lid >> 3) & 1;

    int aRow[4], bRow[2];
    #pragma unroll
    for (int i = 0; i < 4; i++) aRow[i] = warpM * 64 + i * 16 + aRowIn;
    #pragma unroll
    for (int j = 0; j < 2; j++) bRow[j] = warpN * 32 + j * 16 + bRowIn;

    for (int c = 0; c < CH; c++) {
        cpa_wait<STAGES - 2>();
        __syncthreads();
        // Single barrier per chunk is sufficient: producer of iteration c+1
        // writes slot (c+3)%3 == c%3, and the barrier above already ordered
        // all warps past iteration c's MMAs on that slot.
        if (c + STAGES - 1 < CH) {
            LOAD_STAGE(c + STAGES - 1);
        } else {
            cpa_commit();
        }

        const int slot = c % STAGES;
        const uint32_t aB = tile0 + slot * STAGE_BYTES;
        const uint32_t bB = aB + ATILE;

        #pragma unroll
        for (int ks = 0; ks < 4; ks++) {
            uint32_t aF[4][4], bF[2][4];
            #pragma unroll
            for (int i = 0; i < 4; i++) {
                int c16 = ks * 2 + aC16add;
                ldmx4(aF[i], aB + aRow[i] * 128 + (((c16 ^ (aRow[i] & 7)) << 4)));
            }
            #pragma unroll
            for (int j = 0; j < 2; j++) {
                int c16 = ks * 2 + bC16add;
                ldmx4(bF[j], bB + bRow[j] * 128 + (((c16 ^ (bRow[j] & 7)) << 4)));
            }
            #pragma unroll
            for (int i = 0; i < 4; i++)
                #pragma unroll
                for (int jj = 0; jj < 4; jj++)
                    mma16816(acc[i][jj], aF[i], &bF[jj >> 1][(jj & 1) * 2]);
        }
    }

    // ---- epilogue ----
    const int rq = lid >> 2;
    const int cq = (lid & 3) * 2;
    #pragma unroll
    for (int i = 0; i < 4; i++) {
        int m0 = rowBase + warpM * 64 + i * 16 + rq;
        #pragma unroll
        for (int j = 0; j < 4; j++) {
            int col = colBase + warpN * 32 + j * 8 + cq;
            float b0 = bias[col], b1 = bias[col + 1];
            float v00 = acc[i][j][0] + b0, v01 = acc[i][j][1] + b1;
            float v10 = acc[i][j][2] + b0, v11 = acc[i][j][3] + b1;
            if (RELU) {
                v00 = fmaxf(v00, 0.f); v01 = fmaxf(v01, 0.f);
                v10 = fmaxf(v10, 0.f); v11 = fmaxf(v11, 0.f);
            }
            if (BF16OUT) {
                __nv_bfloat16* O = (__nv_bfloat16*)Cout;
                *(__nv_bfloat162*)(O + (size_t)m0 * ldc + col)       = __floats2bfloat162_rn(v00, v01);
                *(__nv_bfloat162*)(O + (size_t)(m0 + 8) * ldc + col) = __floats2bfloat162_rn(v10, v11);
            } else {
                float* O = (float*)Cout;
                *(float2*)(O + (size_t)m0 * ldc + col)       = make_float2(v00, v01);
                *(float2*)(O + (size_t)(m0 + 8) * ldc + col) = make_float2(v10, v11);
            }
        }
    }
    #undef LOAD_STAGE
}

// ---------------- prep kernels ----------------
__global__ void convert_X(const float* __restrict__ X) {
    // only real rows; pad rows of g_Xb stay zero (never written)
    size_t i = (size_t)blockIdx.x * blockDim.x + threadIdx.x;
    size_t total = (size_t)ROWS * FEAT / 4;
    if (i >= total) return;
    size_t off = i * 4;
    float4 v = *(const float4*)(X + off);
    __nv_bfloat162 a = __floats2bfloat162_rn(v.x, v.y);
    __nv_bfloat162 b = __floats2bfloat162_rn(v.z, v.w);
    uint2 pk = make_uint2(*(uint32_t*)&a, *(uint32_t*)&b);
    *(uint2*)(g_Xb + off) = pk;
}

__global__ void transpose_bf16(const float* __restrict__ in, __nv_bfloat16* __restrict__ out,
                               int R, int C) {
    __shared__ float t[32][33];
    int c0 = blockIdx.x * 32, r0 = blockIdx.y * 32;
    int tx = threadIdx.x, ty = threadIdx.y;
    for (int dy = 0; dy < 32; dy += 8)
        t[ty + dy][tx] = in[(size_t)(r0 + ty + dy) * C + c0 + tx];
    __syncthreads();
    for (int dy = 0; dy < 32; dy += 8)
        out[(size_t)(c0 + ty + dy) * R + r0 + tx] = __float2bfloat16_rn(t[tx][ty + dy]);
}

__global__ void pack_head(const float* __restrict__ Wc, const float* __restrict__ bc,
                          const float* __restrict__ Wb, const float* __restrict__ bb) {
    int i = blockIdx.x * blockDim.x + threadIdx.x;
    if (i < HEADN * HID) {
        int n = i / HID, k = i % HID;
        float v = 0.f;
        if (n < NCLS) v = Wc[(size_t)k * NCLS + n];
        else if (n < NCLS + 4) v = Wb[(size_t)k * 4 + (n - NCLS)];
        g_Wcbt[i] = __float2bfloat16_rn(v);
    }
    if (i < HEADN) {
        float v = 0.f;
        if (i < NCLS) v = bc[i];
        else if (i < NCLS + 4) v = bb[i - NCLS];
        g_bcb[i] = v;
    }
}

// ---------------- labeling / sampling ----------------
__global__ void assign_kernel(const float* __restrict__ prop,
                              const float* __restrict__ gtb,
                              const int*   __restrict__ gtl) {
    int idx = blockIdx.x * blockDim.x + threadIdx.x;
    if (idx == 0) { g_loss[0] = 0.f; g_loss[1] = 0.f; g_done = 0u; }
    if (idx >= ROWS) return;
    int b = idx / NN;
    const float* p = prop + (size_t)idx * 4;
    float px1 = p[0], py1 = p[1], px2 = p[2], py2 = p[3];
    float ap = (px2 - px1) * (py2 - py1);
    float best = -1e30f; int bi = 0;
    for (int g = 0; g < GG; g++) {
        const float* gb = gtb + (size_t)(b * GG + g) * 4;
        float x1 = fmaxf(px1, gb[0]);
        float y1 = fmaxf(py1, gb[1]);
        float x2 = fminf(px2, gb[2]);
        float y2 = fminf(py2, gb[3]);
        float inter = fmaxf(x2 - x1, 0.f) * fmaxf(y2 - y1, 0.f);
        float ag = (gb[2] - gb[0]) * (gb[3] - gb[1]);
        float iou = inter / (ap + ag - inter);
        if (iou > best) { best = iou; bi = g; }
    }
    bool fg = best > THR;
    g_label[idx] = fg ? gtl[b * GG + bi] : 0;
    const float* gb = gtb + (size_t)(b * GG + bi) * 4;
    g_mbox[idx * 4 + 0] = fg ? gb[0] : 0.f;
    g_mbox[idx * 4 + 1] = fg ? gb[1] : 0.f;
    g_mbox[idx * 4 + 2] = fg ? gb[2] : 0.f;
    g_mbox[idx * 4 + 3] = fg ? gb[3] : 0.f;
}

__global__ __launch_bounds__(1024) void sample_kernel() {
    int b = blockIdx.x;
    __shared__ int sp[2048];
    __shared__ int sn[2048];
    int tid = threadIdx.x;
    int i0 = tid, i1 = tid + 1024;
    int l0 = (i0 < NN) ? g_label[b * NN + i0] : -1;
    int l1 = (i1 < NN) ? g_label[b * NN + i1] : -1;
    sp[i0] = (i0 < NN && l0 >= 1) ? 1 : 0;
    sn[i0] = (i0 < NN && l0 == 0) ? 1 : 0;
    sp[i1] = (i1 < NN && l1 >= 1) ? 1 : 0;
    sn[i1] = (i1 < NN && l1 == 0) ? 1 : 0;
    __syncthreads();
    for (int off = 1; off < 2048; off <<= 1) {
        int a0 = (i0 >= off) ? sp[i0 - off] : 0;
        int c0 = (i0 >= off) ? sn[i0 - off] : 0;
        int a1 = (i1 >= off) ? sp[i1 - off] : 0;
        int c1 = (i1 >= off) ? sn[i1 - off] : 0;
        __syncthreads();
        sp[i0] += a0; sn[i0] += c0; sp[i1] += a1; sn[i1] += c1;
        __syncthreads();
    }
    if (i0 < NN) {
        bool kp = (l0 >= 1) && (sp[i0] <= NUM_POS);
        bool kn = (l0 == 0) && (sn[i0] <= NUM_NEG);
        g_samp[b * NN + i0] = kp ? l0 : (kn ? 0 : -1);
    }
    if (i1 < NN) {
        bool kp = (l1 >= 1) && (sp[i1] <= NUM_POS);
        bool kn = (l1 == 0) && (sn[i1] <= NUM_NEG);
        g_samp[b * NN + i1] = kp ? l1 : (kn ? 0 : -1);
    }
}

// ---------------- per-row loss + fused finalize ----------------
#define LOSS_BLOCKS ((ROWS + 255) / 256)

__global__ void loss_kernel(const float* __restrict__ prop, float* __restrict__ out) {
    int r = blockIdx.x * blockDim.x + threadIdx.x;
    if (r < ROWS) {
        const float* lg = g_logits + (size_t)r * HEADN;

        float mx = -1e30f;
        for (int c = 0; c < NCLS; c++) mx = fmaxf(mx, lg[c]);
        float s = 0.f;
        float p[NCLS];
        for (int c = 0; c < NCLS; c++) { p[c] = expf(lg[c] - mx); s += p[c]; }
        float inv = 1.f / s;
        for (int c = 0; c < NCLS; c++) p[c] *= inv;
        float mx2 = -1e30f;
        for (int c = 0; c < NCLS; c++) mx2 = fmaxf(mx2, p[c]);
        float s2 = 0.f;
        for (int c = 0; c < NCLS; c++) s2 += expf(p[c] - mx2);
        float logZ = mx2 + logf(s2);

        int sv = g_samp[r];
        int tgt = sv > 0 ? sv : 0;
        float cls = (sv >= 0) ? (logZ - p[tgt]) : 0.f;

        float loc = 0.f;
        if (sv > 0) {
            const float* pb = prop + (size_t)r * 4;
            const float* gb = g_mbox + (size_t)r * 4;
            float pw  = pb[2] - pb[0];
            float ph  = pb[3] - pb[1];
            float pcx = pb[0] + 0.5f * pw;
            float pcy = pb[1] + 0.5f * ph;
            float gw  = gb[2] - gb[0];
            float gh  = gb[3] - gb[1];
            float gcx = 0.5f * (gb[0] + gb[2]);
            float gcy = 0.5f * (gb[1] + gb[3]);
            float gt_d[4];
            gt_d[0] = (gcx - pcx) / pw;
            gt_d[1] = (gcy - pcy) / ph;
            gt_d[2] = logf(gw / pw);
            gt_d[3] = logf(gh / ph);
            for (int c = 0; c < 4; c++) {
                float d  = lg[NCLS + c] - gt_d[c];
                float ad = fabsf(d);
                loc += (ad < 1.f) ? 0.5f * d * d : (ad - 0.5f);
            }
        }
        if (cls != 0.f) atomicAdd(&g_loss[0], cls);
        if (loc != 0.f) atomicAdd(&g_loss[1], loc);
    }
    // fused finalize: last block to finish writes the output
    __syncthreads();
    if (threadIdx.x == 0) {
        __threadfence();
        unsigned t = atomicAdd(&g_done, 1u);
        if (t == LOSS_BLOCKS - 1) {
            __threadfence();
            out[0] = g_loss[0] / DENOM;
            out[1] = g_loss[1] / DENOM;
        }
    }
}

// ---------------- launch -----------------------------------------------------
extern "C" void kernel_launch(void* const* d_in, const int* in_sizes, int n_in,
                              void* d_out, int out_size) {
    const float* X    = (const float*)d_in[0];
    const float* prop = (const float*)d_in[1];
    const float* gtb  = (const float*)d_in[2];
    const int*   gtl  = (const int*)  d_in[3];
    const float* W1   = (const float*)d_in[4];
    const float* b1   = (const float*)d_in[5];
    const float* W2   = (const float*)d_in[6];
    const float* b2   = (const float*)d_in[7];
    const float* Wc   = (const float*)d_in[8];
    const float* bc   = (const float*)d_in[9];
    const float* Wb   = (const float*)d_in[10];
    const float* bb   = (const float*)d_in[11];
    float* out = (float*)d_out;

    void *pXb, *pW1t, *pW2t, *pWcbt, *pbcb, *ph1, *ph2, *plg;
    cudaGetSymbolAddress(&pXb, g_Xb);
    cudaGetSymbolAddress(&pW1t, g_W1t);
    cudaGetSymbolAddress(&pW2t, g_W2t);
    cudaGetSymbolAddress(&pWcbt, g_Wcbt);
    cudaGetSymbolAddress(&pbcb, g_bcb);
    cudaGetSymbolAddress(&ph1, g_h1b);
    cudaGetSymbolAddress(&ph2, g_h2b);
    cudaGetSymbolAddress(&plg, g_logits);

    cudaFuncSetAttribute(gemm_mma<1, 1>, cudaFuncAttributeMaxDynamicSharedMemorySize, GEMM_SMEM);
    cudaFuncSetAttribute(gemm_mma<0, 0>, cudaFuncAttributeMaxDynamicSharedMemorySize, GEMM_SMEM);

    {
        size_t tot = (size_t)ROWS * FEAT / 4;
        convert_X<<<(unsigned)((tot + 255) / 256), 256>>>(X);
    }
    transpose_bf16<<<dim3(HID / 32, FEAT / 32), dim3(32, 8)>>>(W1, (__nv_bfloat16*)pW1t, FEAT, HID);
    transpose_bf16<<<dim3(HID / 32, HID / 32), dim3(32, 8)>>>(W2, (__nv_bfloat16*)pW2t, HID, HID);
    pack_head<<<(HEADN * HID + 255) / 256, 256>>>(Wc, bc, Wb, bb);

    assign_kernel<<<(ROWS + 255) / 256, 256>>>(prop, gtb, gtl);
    sample_kernel<<<BB, 1024>>>();

    gemm_mma<1, 1><<<dim3(HID / 128, PADM / 128), 256, GEMM_SMEM>>>(
        (const __nv_bfloat16*)pXb, FEAT, (const __nv_bfloat16*)pW1t, FEAT,
        b1, ph1, HID, FEAT);
    gemm_mma<1, 1><<<dim3(HID / 128, PADM / 128), 256, GEMM_SMEM>>>(
        (const __nv_bfloat16*)ph1, HID, (const __nv_bfloat16*)pW2t, HID,
        b2, ph2, HID, HID);
    gemm_mma<0, 0><<<dim3(HEADN / 128, PADM / 128), 256, GEMM_SMEM>>>(
        (const __nv_bfloat16*)ph2, HID, (const __nv_bfloat16*)pWcbt, HID,
        (const float*)pbcb, plg, HEADN, HID);

    loss_kernel<<<LOSS_BLOCKS, 256>>>(prop, out);
}